// round 15
// baseline (speedup 1.0000x reference)
#include <cuda_runtime.h>
#include <cuda_fp16.h>

#define N_USERS 100000
#define N_ITEMS 200000
#define N_NODES (N_USERS + N_ITEMS)
#define DIM 256
#define DIM4 (DIM / 4)
#define DIMH4 (DIM / 8)     // int4 (8 halves) per row = 32
#define N_EDGES 1000000
#define NDIR (2 * N_EDGES)
#define BATCH 8192
#define SCAN_BLK 1024
#define SCAN_NB ((N_NODES + SCAN_BLK - 1) / SCAN_BLK)   // 293
#define SCATTER_BLOCKS ((N_EDGES + 255) / 256)          // 3907
#define INIT_H2 ((size_t)N_NODES * DIM / 2)             // 38.4M half2
#define INIT_BLOCKS ((int)((INIT_H2 + 255) / 256))
#define ZERO_BLOCKS ((N_NODES + 255) / 256)             // 1172
#define MARKB_BLOCKS ((3 * BATCH + 255) / 256)          // 96

// ---------------- device scratch (static: allowed) ----------------
// propagating buffers store p_l = dinv * x_l  (pre-scaled), fp16
__device__ __half g_p0[(size_t)N_NODES * DIM];   // 154 MB
__device__ __half g_p1[(size_t)N_NODES * DIM];   // 154 MB
__device__ __half g_p2[(size_t)N_NODES * DIM];   // 154 MB
__device__ int   g_deg[N_NODES];
__device__ int   g_rowptr[N_NODES + 1];
__device__ int   g_cursor[N_NODES];
__device__ float g_dinv[N_NODES];                // deg^-1/2
__device__ float g_rdeg[N_NODES];                // deg^+1/2 (un-scale factor)
__device__ int   g_csrsrc[NDIR];                 // 8 MB
__device__ int   g_part[SCAN_NB];
// write-once idempotent flags (same batch every call -> identical fixed point)
__device__ unsigned char g_need_b[N_NODES];      // node is a batch node
__device__ unsigned char g_need2[N_NODES];       // p2 needed: batch + 1-hop

// ---------------- accumulator helpers ----------------
struct Acc8 {
    float a0, a1, a2, a3, a4, a5, a6, a7;
    __device__ __forceinline__ void init() {
        a0 = a1 = a2 = a3 = a4 = a5 = a6 = a7 = 0.f;
    }
    __device__ __forceinline__ void add(const int4& raw) {
        float2 f0 = __half22float2(*(__half2*)&raw.x);
        float2 f1 = __half22float2(*(__half2*)&raw.y);
        float2 f2 = __half22float2(*(__half2*)&raw.z);
        float2 f3 = __half22float2(*(__half2*)&raw.w);
        a0 += f0.x; a1 += f0.y; a2 += f1.x; a3 += f1.y;
        a4 += f2.x; a5 += f2.y; a6 += f3.x; a7 += f3.y;
    }
};

// gather-sum over adjacency [beg,end) from fp16 buffer, 4x unrolled for MLP.
// csrsrc uses normal cached loads: all lanes broadcast-read the same element and
// consecutive iterations walk the same 128B line (~32 edges/line) -> real L1 reuse.
__device__ __forceinline__ void gather_sum(const int4* __restrict__ xin, int beg, int end,
                                           int lane, Acc8& acc) {
    int e = beg;
    for (; e + 4 <= end; e += 4) {
        int s0 = g_csrsrc[e];
        int s1 = g_csrsrc[e + 1];
        int s2 = g_csrsrc[e + 2];
        int s3 = g_csrsrc[e + 3];
        int4 r0 = xin[(size_t)s0 * DIMH4 + lane];
        int4 r1 = xin[(size_t)s1 * DIMH4 + lane];
        int4 r2 = xin[(size_t)s2 * DIMH4 + lane];
        int4 r3 = xin[(size_t)s3 * DIMH4 + lane];
        acc.add(r0);
        acc.add(r1);
        acc.add(r2);
        acc.add(r3);
    }
    for (; e < end; e++) {
        int s = g_csrsrc[e];
        int4 r = xin[(size_t)s * DIMH4 + lane];
        acc.add(r);
    }
}

// ---------------- 1: zero degrees + mark batch nodes (disjoint block ranges) ----------
__global__ void k_zero_mark(const int* __restrict__ uidx, const int* __restrict__ pidx,
                            const int* __restrict__ nidx) {
    if (blockIdx.x < ZERO_BLOCKS) {
        int i = blockIdx.x * 256 + threadIdx.x;
        if (i < N_NODES) g_deg[i] = 0;
    } else {
        int j = (blockIdx.x - ZERO_BLOCKS) * 256 + threadIdx.x;
        if (j < 3 * BATCH) {
            int node;
            if (j < BATCH) node = uidx[j];
            else if (j < 2 * BATCH) node = N_USERS + pidx[j - BATCH];
            else node = N_USERS + nidx[j - 2 * BATCH];
            g_need_b[node] = 1;   // idempotent
            g_need2[node] = 1;    // batch nodes need p2 themselves
        }
    }
}

// ---------------- 2: count degrees + mark 1-hop neighbors of batch nodes --------------
__global__ void k_count_mark(const int* __restrict__ erow, const int* __restrict__ ecol) {
    int e = blockIdx.x * blockDim.x + threadIdx.x;
    if (e < N_EDGES) {
        int u = erow[e];
        int it = N_USERS + ecol[e];
        atomicAdd(&g_deg[u], 1);
        atomicAdd(&g_deg[it], 1);
        if (g_need_b[u]) g_need2[it] = 1;   // idempotent byte stores
        if (g_need_b[it]) g_need2[u] = 1;
    }
}

// ---------------- 3: per-block scan (within-block exclusive + block totals) -----------
__global__ void k_scan1() {
    __shared__ int s[SCAN_BLK];
    int tid = threadIdx.x;
    int i = blockIdx.x * SCAN_BLK + tid;
    int v = (i < N_NODES) ? g_deg[i] : 0;
    s[tid] = v;
    __syncthreads();
    for (int off = 1; off < SCAN_BLK; off <<= 1) {
        int t = (tid >= off) ? s[tid - off] : 0;
        __syncthreads();
        s[tid] += t;
        __syncthreads();
    }
    if (i < N_NODES) g_rowptr[i] = s[tid] - v;
    if (tid == SCAN_BLK - 1) g_part[blockIdx.x] = s[tid];
}

// ---------------- 4: finalize scan: inline partial-prefix reduce + dinv/rdeg ----------
// 256-thread blocks; all nodes of a block share one part-prefix (k = blockIdx>>2).
__global__ void __launch_bounds__(256) k_scan3() {
    __shared__ int s[256];
    int tid = threadIdx.x;
    int k = blockIdx.x >> 2;              // number of preceding SCAN_BLK partitions
    int v = 0;
    if (tid < k) v = g_part[tid];
    if (tid + 256 < k) v += g_part[tid + 256];   // k <= 293 < 512
    s[tid] = v;
    __syncthreads();
    for (int off = 128; off > 0; off >>= 1) {
        if (tid < off) s[tid] += s[tid + off];
        __syncthreads();
    }
    int prefix = s[0];

    int i = blockIdx.x * 256 + tid;
    if (i < N_NODES) {
        int rp = g_rowptr[i] + prefix;
        g_rowptr[i] = rp;
        g_cursor[i] = rp;
        int d = g_deg[i];
        float df = (float)(d < 1 ? 1 : d);
        g_dinv[i] = rsqrtf(df);
        g_rdeg[i] = sqrtf(df);
    }
    if (i == 0) g_rowptr[N_NODES] = NDIR;
}

// ---------------- 5: fused CSR scatter (latency-bound) || p0 init (BW-bound) ----------
__global__ void __launch_bounds__(256) k_scatter_init(
        const int* __restrict__ erow, const int* __restrict__ ecol,
        const float* __restrict__ uemb, const float* __restrict__ iemb) {
    if (blockIdx.x < SCATTER_BLOCKS) {
        int e = blockIdx.x * 256 + threadIdx.x;
        if (e < N_EDGES) {
            int u = erow[e];
            int it = N_USERS + ecol[e];
            int p = atomicAdd(&g_cursor[u], 1);
            g_csrsrc[p] = it;
            int q = atomicAdd(&g_cursor[it], 1);
            g_csrsrc[q] = u;
        }
    } else {
        size_t i = (size_t)(blockIdx.x - SCATTER_BLOCKS) * 256 + threadIdx.x;  // half2 idx
        if (i >= INIT_H2) return;
        size_t ei = i * 2;
        size_t row = ei >> 8;
        float d = g_dinv[row];
        float2 v;
        if (ei < (size_t)N_USERS * DIM) v = ((const float2*)uemb)[i];
        else v = ((const float2*)iemb)[i - (size_t)N_USERS * DIM / 2];
        ((__half2*)g_p0)[i] = __floats2half2_rn(v.x * d, v.y * d);
    }
}

// ---------------- 6/7: full propagation, p_out[dst] = half(dinv^2 * sum_src p_in[src]) -
// 64-thread blocks (2 warps): minimal block-retire tail under degree variance while
// keeping full occupancy (32 CTAs/SM x 64 thr = 2048 thr/SM).
__global__ void __launch_bounds__(64) k_spmm_full(int which, int use_flag) {
    const int4* __restrict__ xin = (const int4*)(which == 0 ? g_p0 : g_p1);
    int4* __restrict__ xout = (int4*)(which == 0 ? g_p1 : g_p2);

    int row = blockIdx.x * 2 + (threadIdx.x >> 5);
    int lane = threadIdx.x & 31;
    if (row >= N_NODES) return;
    if (use_flag && !g_need2[row]) return;

    int beg = g_rowptr[row];
    int end = g_rowptr[row + 1];
    float di = g_dinv[row];
    float w = di * di;

    Acc8 acc;
    acc.init();
    gather_sum(xin, beg, end, lane, acc);

    int4 out;
    __half2 o0 = __floats2half2_rn(acc.a0 * w, acc.a1 * w);
    __half2 o1 = __floats2half2_rn(acc.a2 * w, acc.a3 * w);
    __half2 o2 = __floats2half2_rn(acc.a4 * w, acc.a5 * w);
    __half2 o3 = __floats2half2_rn(acc.a6 * w, acc.a7 * w);
    out.x = *(int*)&o0; out.y = *(int*)&o1; out.z = *(int*)&o2; out.w = *(int*)&o3;
    xout[(size_t)row * DIMH4 + lane] = out;   // normal store: re-read by next kernel
}

// ---------------- 8: fused finalize ----------------
__device__ __forceinline__ void load8h(const int4* base, size_t row, int lane, float* f) {
    int4 raw = base[row * DIMH4 + lane];
    float2 f0 = __half22float2(*(__half2*)&raw.x);
    float2 f1 = __half22float2(*(__half2*)&raw.y);
    float2 f2 = __half22float2(*(__half2*)&raw.z);
    float2 f3 = __half22float2(*(__half2*)&raw.w);
    f[0] = f0.x; f[1] = f0.y; f[2] = f1.x; f[3] = f1.y;
    f[4] = f2.x; f[5] = f2.y; f[6] = f3.x; f[7] = f3.y;
}

__device__ __forceinline__ void node_acc(int node, const float4* __restrict__ emb4,
                                         size_t embrow, int lane,
                                         float* accv, float4* __restrict__ rawout) {
    const int4* p1h = (const int4*)g_p1;
    const int4* p2h = (const int4*)g_p2;

    int beg = g_rowptr[node];
    int end = g_rowptr[node + 1];
    float di = g_dinv[node];
    float rd = g_rdeg[node];

    Acc8 acc;
    acc.init();
    gather_sum(p2h, beg, end, lane, acc);
    float x3[8] = {acc.a0 * di, acc.a1 * di, acc.a2 * di, acc.a3 * di,
                   acc.a4 * di, acc.a5 * di, acc.a6 * di, acc.a7 * di};

    float4 e0 = emb4[embrow * DIM4 + lane * 2];
    float4 e1 = emb4[embrow * DIM4 + lane * 2 + 1];
    float e[8] = {e0.x, e0.y, e0.z, e0.w, e1.x, e1.y, e1.z, e1.w};

    float t1[8], t2[8];
    load8h(p1h, (size_t)node, lane, t1);
    load8h(p2h, (size_t)node, lane, t2);
#pragma unroll
    for (int k = 0; k < 8; k++) accv[k] = e[k] + (t1[k] + t2[k]) * rd + x3[k];

    __stcs(&rawout[lane * 2], e0);        // out buffer is write-only: stream it
    __stcs(&rawout[lane * 2 + 1], e1);
}

__global__ void __launch_bounds__(64) k_finalize(
        const int* __restrict__ uidx, const int* __restrict__ pidx,
        const int* __restrict__ nidx,
        const float* __restrict__ uemb, const float* __restrict__ iemb,
        float* __restrict__ out) {
    int b = blockIdx.x * 2 + (threadIdx.x >> 5);
    int lane = threadIdx.x & 31;
    if (b >= BATCH) return;

    int u = uidx[b];
    int pi = pidx[b];
    int ni = nidx[b];

    float4* oue = (float4*)(out + 2 * BATCH) + (size_t)b * DIM4;
    float4* ope = (float4*)(out + 2 * BATCH + (size_t)BATCH * DIM) + (size_t)b * DIM4;
    float4* one_ = (float4*)(out + 2 * BATCH + (size_t)2 * BATCH * DIM) + (size_t)b * DIM4;

    float au[8], ap[8], an[8];
    node_acc(u, (const float4*)uemb, (size_t)u, lane, au, oue);
    node_acc(N_USERS + pi, (const float4*)iemb, (size_t)pi, lane, ap, ope);
    node_acc(N_USERS + ni, (const float4*)iemb, (size_t)ni, lane, an, one_);

    float ps = 0.f, ns = 0.f;
#pragma unroll
    for (int k = 0; k < 8; k++) {
        ps += au[k] * ap[k];
        ns += au[k] * an[k];
    }
#pragma unroll
    for (int off = 16; off > 0; off >>= 1) {
        ps += __shfl_down_sync(0xFFFFFFFFu, ps, off);
        ns += __shfl_down_sync(0xFFFFFFFFu, ns, off);
    }
    const float inv16 = 1.0f / 16.0f;   // (1/(N_LAYERS+1))^2
    if (lane == 0) {
        out[b] = ps * inv16;
        out[BATCH + b] = ns * inv16;
    }
}

// ---------------- launch ----------------
extern "C" void kernel_launch(void* const* d_in, const int* in_sizes, int n_in,
                              void* d_out, int out_size) {
    const float* user_emb = (const float*)d_in[0];
    const float* item_emb = (const float*)d_in[1];
    const int* edge_row = (const int*)d_in[2];
    const int* edge_col = (const int*)d_in[3];
    const int* users_idx = (const int*)d_in[4];
    const int* pos_idx = (const int*)d_in[5];
    const int* neg_idx = (const int*)d_in[6];
    float* out = (float*)d_out;

    // 1: zero degrees + mark batch nodes
    k_zero_mark<<<ZERO_BLOCKS + MARKB_BLOCKS, 256>>>(users_idx, pos_idx, neg_idx);
    // 2: count degrees + mark need2 = batch + 1-hop
    k_count_mark<<<(N_EDGES + 255) / 256, 256>>>(edge_row, edge_col);
    // 3-4: scan (block partials, then fused prefix+finalize)
    k_scan1<<<SCAN_NB, SCAN_BLK>>>();
    k_scan3<<<(N_NODES + 255) / 256, 256>>>();
    // 5: fused CSR scatter || p0 = half(dinv * x0)
    k_scatter_init<<<SCATTER_BLOCKS + INIT_BLOCKS, 256>>>(edge_row, edge_col,
                                                          user_emb, item_emb);
    // 6-7: layer 1 full; layer 2 only at marked rows (64-thread blocks, 2 rows each)
    int spmm_blocks = (N_NODES + 1) / 2;
    k_spmm_full<<<spmm_blocks, 64>>>(0, 0);   // p0 -> p1 (all rows)
    k_spmm_full<<<spmm_blocks, 64>>>(1, 1);   // p1 -> p2 (marked rows only)
    // 8: fused sparse layer 3 + outputs (2 batch elems per 64-thread block)
    k_finalize<<<BATCH / 2, 64>>>(users_idx, pos_idx, neg_idx, user_emb, item_emb, out);
}

// round 16
// speedup vs baseline: 1.0567x; 1.0567x over previous
#include <cuda_runtime.h>
#include <cuda_fp16.h>

#define N_USERS 100000
#define N_ITEMS 200000
#define N_NODES (N_USERS + N_ITEMS)
#define DIM 256
#define DIM4 (DIM / 4)
#define DIMH4 (DIM / 8)     // int4 (8 halves) per row = 32
#define N_EDGES 1000000
#define NDIR (2 * N_EDGES)
#define BATCH 8192
#define SCAN_BLK 1024
#define SCAN_NB ((N_NODES + SCAN_BLK - 1) / SCAN_BLK)   // 293
#define SCATTER_BLOCKS ((N_EDGES + 255) / 256)          // 3907
#define INIT_H2 ((size_t)N_NODES * DIM / 2)             // 38.4M half2
#define INIT_BLOCKS ((int)((INIT_H2 + 255) / 256))
#define ZERO_BLOCKS ((N_NODES + 255) / 256)             // 1172
#define MARKB_BLOCKS ((3 * BATCH + 255) / 256)          // 96

// ---------------- device scratch (static: allowed) ----------------
// propagating buffers store p_l = dinv * x_l  (pre-scaled), fp16
__device__ __half g_p0[(size_t)N_NODES * DIM];   // 154 MB
__device__ __half g_p1[(size_t)N_NODES * DIM];   // 154 MB
__device__ __half g_p2[(size_t)N_NODES * DIM];   // 154 MB
__device__ int   g_deg[N_NODES];
__device__ int   g_rowptr[N_NODES + 1];
__device__ int   g_cursor[N_NODES];
__device__ float g_dinv[N_NODES];                // deg^-1/2
__device__ float g_rdeg[N_NODES];                // deg^+1/2 (un-scale factor)
__device__ int   g_csrsrc[NDIR];                 // 8 MB
__device__ int   g_part[SCAN_NB];
// write-once idempotent flags (same batch every call -> identical fixed point)
__device__ unsigned char g_need_b[N_NODES];      // node is a batch node
__device__ unsigned char g_need2[N_NODES];       // p2 needed: batch + 1-hop

// ---------------- accumulator helpers ----------------
struct Acc8 {
    float a0, a1, a2, a3, a4, a5, a6, a7;
    __device__ __forceinline__ void init() {
        a0 = a1 = a2 = a3 = a4 = a5 = a6 = a7 = 0.f;
    }
    __device__ __forceinline__ void add(const int4& raw) {
        float2 f0 = __half22float2(*(__half2*)&raw.x);
        float2 f1 = __half22float2(*(__half2*)&raw.y);
        float2 f2 = __half22float2(*(__half2*)&raw.z);
        float2 f3 = __half22float2(*(__half2*)&raw.w);
        a0 += f0.x; a1 += f0.y; a2 += f1.x; a3 += f1.y;
        a4 += f2.x; a5 += f2.y; a6 += f3.x; a7 += f3.y;
    }
};

// gather-sum over adjacency [beg,end) from fp16 buffer, 4x unrolled for MLP.
// csrsrc uses normal cached loads: all lanes broadcast-read the same element and
// consecutive iterations walk the same 128B line (~32 edges/line) -> real L1 reuse.
__device__ __forceinline__ void gather_sum(const int4* __restrict__ xin, int beg, int end,
                                           int lane, Acc8& acc) {
    int e = beg;
    for (; e + 4 <= end; e += 4) {
        int s0 = g_csrsrc[e];
        int s1 = g_csrsrc[e + 1];
        int s2 = g_csrsrc[e + 2];
        int s3 = g_csrsrc[e + 3];
        int4 r0 = xin[(size_t)s0 * DIMH4 + lane];
        int4 r1 = xin[(size_t)s1 * DIMH4 + lane];
        int4 r2 = xin[(size_t)s2 * DIMH4 + lane];
        int4 r3 = xin[(size_t)s3 * DIMH4 + lane];
        acc.add(r0);
        acc.add(r1);
        acc.add(r2);
        acc.add(r3);
    }
    for (; e < end; e++) {
        int s = g_csrsrc[e];
        int4 r = xin[(size_t)s * DIMH4 + lane];
        acc.add(r);
    }
}

// ---------------- 1: zero degrees + mark batch nodes (disjoint block ranges) ----------
__global__ void k_zero_mark(const int* __restrict__ uidx, const int* __restrict__ pidx,
                            const int* __restrict__ nidx) {
    if (blockIdx.x < ZERO_BLOCKS) {
        int i = blockIdx.x * 256 + threadIdx.x;
        if (i < N_NODES) g_deg[i] = 0;
    } else {
        int j = (blockIdx.x - ZERO_BLOCKS) * 256 + threadIdx.x;
        if (j < 3 * BATCH) {
            int node;
            if (j < BATCH) node = uidx[j];
            else if (j < 2 * BATCH) node = N_USERS + pidx[j - BATCH];
            else node = N_USERS + nidx[j - 2 * BATCH];
            g_need_b[node] = 1;   // idempotent
            g_need2[node] = 1;    // batch nodes need p2 themselves
        }
    }
}

// ---------------- 2: count degrees + mark 1-hop neighbors of batch nodes --------------
__global__ void k_count_mark(const int* __restrict__ erow, const int* __restrict__ ecol) {
    int e = blockIdx.x * blockDim.x + threadIdx.x;
    if (e < N_EDGES) {
        int u = erow[e];
        int it = N_USERS + ecol[e];
        atomicAdd(&g_deg[u], 1);
        atomicAdd(&g_deg[it], 1);
        if (g_need_b[u]) g_need2[it] = 1;   // idempotent byte stores
        if (g_need_b[it]) g_need2[u] = 1;
    }
}

// ---------------- 3: per-block scan (within-block exclusive + block totals) -----------
__global__ void k_scan1() {
    __shared__ int s[SCAN_BLK];
    int tid = threadIdx.x;
    int i = blockIdx.x * SCAN_BLK + tid;
    int v = (i < N_NODES) ? g_deg[i] : 0;
    s[tid] = v;
    __syncthreads();
    for (int off = 1; off < SCAN_BLK; off <<= 1) {
        int t = (tid >= off) ? s[tid - off] : 0;
        __syncthreads();
        s[tid] += t;
        __syncthreads();
    }
    if (i < N_NODES) g_rowptr[i] = s[tid] - v;
    if (tid == SCAN_BLK - 1) g_part[blockIdx.x] = s[tid];
}

// ---------------- 4: finalize scan: inline partial-prefix reduce + dinv/rdeg ----------
// 256-thread blocks; all nodes of a block share one part-prefix (k = blockIdx>>2).
__global__ void __launch_bounds__(256) k_scan3() {
    __shared__ int s[256];
    int tid = threadIdx.x;
    int k = blockIdx.x >> 2;              // number of preceding SCAN_BLK partitions
    int v = 0;
    if (tid < k) v = g_part[tid];
    if (tid + 256 < k) v += g_part[tid + 256];   // k <= 293 < 512
    s[tid] = v;
    __syncthreads();
    for (int off = 128; off > 0; off >>= 1) {
        if (tid < off) s[tid] += s[tid + off];
        __syncthreads();
    }
    int prefix = s[0];

    int i = blockIdx.x * 256 + tid;
    if (i < N_NODES) {
        int rp = g_rowptr[i] + prefix;
        g_rowptr[i] = rp;
        g_cursor[i] = rp;
        int d = g_deg[i];
        float df = (float)(d < 1 ? 1 : d);
        g_dinv[i] = rsqrtf(df);
        g_rdeg[i] = sqrtf(df);
    }
    if (i == 0) g_rowptr[N_NODES] = NDIR;
}

// ---------------- 5: fused CSR scatter (latency-bound) || p0 init (BW-bound) ----------
__global__ void __launch_bounds__(256) k_scatter_init(
        const int* __restrict__ erow, const int* __restrict__ ecol,
        const float* __restrict__ uemb, const float* __restrict__ iemb) {
    if (blockIdx.x < SCATTER_BLOCKS) {
        int e = blockIdx.x * 256 + threadIdx.x;
        if (e < N_EDGES) {
            int u = erow[e];
            int it = N_USERS + ecol[e];
            int p = atomicAdd(&g_cursor[u], 1);
            g_csrsrc[p] = it;
            int q = atomicAdd(&g_cursor[it], 1);
            g_csrsrc[q] = u;
        }
    } else {
        size_t i = (size_t)(blockIdx.x - SCATTER_BLOCKS) * 256 + threadIdx.x;  // half2 idx
        if (i >= INIT_H2) return;
        size_t ei = i * 2;
        size_t row = ei >> 8;
        float d = g_dinv[row];
        float2 v;
        if (ei < (size_t)N_USERS * DIM) v = ((const float2*)uemb)[i];
        else v = ((const float2*)iemb)[i - (size_t)N_USERS * DIM / 2];
        ((__half2*)g_p0)[i] = __floats2half2_rn(v.x * d, v.y * d);
    }
}

// ---------------- 6/7: full propagation, p_out[dst] = half(dinv^2 * sum_src p_in[src]) -
// 128-thread blocks (4 warps): measured optimum (256->428us, 128->406us, 64->430us).
__global__ void __launch_bounds__(128) k_spmm_full(int which, int use_flag) {
    const int4* __restrict__ xin = (const int4*)(which == 0 ? g_p0 : g_p1);
    int4* __restrict__ xout = (int4*)(which == 0 ? g_p1 : g_p2);

    int row = blockIdx.x * 4 + (threadIdx.x >> 5);
    int lane = threadIdx.x & 31;
    if (row >= N_NODES) return;
    if (use_flag && !g_need2[row]) return;

    int beg = g_rowptr[row];
    int end = g_rowptr[row + 1];
    float di = g_dinv[row];
    float w = di * di;

    Acc8 acc;
    acc.init();
    gather_sum(xin, beg, end, lane, acc);

    int4 out;
    __half2 o0 = __floats2half2_rn(acc.a0 * w, acc.a1 * w);
    __half2 o1 = __floats2half2_rn(acc.a2 * w, acc.a3 * w);
    __half2 o2 = __floats2half2_rn(acc.a4 * w, acc.a5 * w);
    __half2 o3 = __floats2half2_rn(acc.a6 * w, acc.a7 * w);
    out.x = *(int*)&o0; out.y = *(int*)&o1; out.z = *(int*)&o2; out.w = *(int*)&o3;
    xout[(size_t)row * DIMH4 + lane] = out;   // normal store: re-read by next kernel
}

// ---------------- 8: fused finalize ----------------
__device__ __forceinline__ void load8h(const int4* base, size_t row, int lane, float* f) {
    int4 raw = base[row * DIMH4 + lane];
    float2 f0 = __half22float2(*(__half2*)&raw.x);
    float2 f1 = __half22float2(*(__half2*)&raw.y);
    float2 f2 = __half22float2(*(__half2*)&raw.z);
    float2 f3 = __half22float2(*(__half2*)&raw.w);
    f[0] = f0.x; f[1] = f0.y; f[2] = f1.x; f[3] = f1.y;
    f[4] = f2.x; f[5] = f2.y; f[6] = f3.x; f[7] = f3.y;
}

__device__ __forceinline__ void node_acc(int node, const float4* __restrict__ emb4,
                                         size_t embrow, int lane,
                                         float* accv, float4* __restrict__ rawout) {
    const int4* p1h = (const int4*)g_p1;
    const int4* p2h = (const int4*)g_p2;

    int beg = g_rowptr[node];
    int end = g_rowptr[node + 1];
    float di = g_dinv[node];
    float rd = g_rdeg[node];

    Acc8 acc;
    acc.init();
    gather_sum(p2h, beg, end, lane, acc);
    float x3[8] = {acc.a0 * di, acc.a1 * di, acc.a2 * di, acc.a3 * di,
                   acc.a4 * di, acc.a5 * di, acc.a6 * di, acc.a7 * di};

    float4 e0 = emb4[embrow * DIM4 + lane * 2];
    float4 e1 = emb4[embrow * DIM4 + lane * 2 + 1];
    float e[8] = {e0.x, e0.y, e0.z, e0.w, e1.x, e1.y, e1.z, e1.w};

    float t1[8], t2[8];
    load8h(p1h, (size_t)node, lane, t1);
    load8h(p2h, (size_t)node, lane, t2);
#pragma unroll
    for (int k = 0; k < 8; k++) accv[k] = e[k] + (t1[k] + t2[k]) * rd + x3[k];

    __stcs(&rawout[lane * 2], e0);        // out buffer is write-only: stream it
    __stcs(&rawout[lane * 2 + 1], e1);
}

__global__ void __launch_bounds__(128) k_finalize(
        const int* __restrict__ uidx, const int* __restrict__ pidx,
        const int* __restrict__ nidx,
        const float* __restrict__ uemb, const float* __restrict__ iemb,
        float* __restrict__ out) {
    int b = blockIdx.x * 4 + (threadIdx.x >> 5);
    int lane = threadIdx.x & 31;
    if (b >= BATCH) return;

    int u = uidx[b];
    int pi = pidx[b];
    int ni = nidx[b];

    float4* oue = (float4*)(out + 2 * BATCH) + (size_t)b * DIM4;
    float4* ope = (float4*)(out + 2 * BATCH + (size_t)BATCH * DIM) + (size_t)b * DIM4;
    float4* one_ = (float4*)(out + 2 * BATCH + (size_t)2 * BATCH * DIM) + (size_t)b * DIM4;

    float au[8], ap[8], an[8];
    node_acc(u, (const float4*)uemb, (size_t)u, lane, au, oue);
    node_acc(N_USERS + pi, (const float4*)iemb, (size_t)pi, lane, ap, ope);
    node_acc(N_USERS + ni, (const float4*)iemb, (size_t)ni, lane, an, one_);

    float ps = 0.f, ns = 0.f;
#pragma unroll
    for (int k = 0; k < 8; k++) {
        ps += au[k] * ap[k];
        ns += au[k] * an[k];
    }
#pragma unroll
    for (int off = 16; off > 0; off >>= 1) {
        ps += __shfl_down_sync(0xFFFFFFFFu, ps, off);
        ns += __shfl_down_sync(0xFFFFFFFFu, ns, off);
    }
    const float inv16 = 1.0f / 16.0f;   // (1/(N_LAYERS+1))^2
    if (lane == 0) {
        out[b] = ps * inv16;
        out[BATCH + b] = ns * inv16;
    }
}

// ---------------- launch ----------------
extern "C" void kernel_launch(void* const* d_in, const int* in_sizes, int n_in,
                              void* d_out, int out_size) {
    const float* user_emb = (const float*)d_in[0];
    const float* item_emb = (const float*)d_in[1];
    const int* edge_row = (const int*)d_in[2];
    const int* edge_col = (const int*)d_in[3];
    const int* users_idx = (const int*)d_in[4];
    const int* pos_idx = (const int*)d_in[5];
    const int* neg_idx = (const int*)d_in[6];
    float* out = (float*)d_out;

    // 1: zero degrees + mark batch nodes
    k_zero_mark<<<ZERO_BLOCKS + MARKB_BLOCKS, 256>>>(users_idx, pos_idx, neg_idx);
    // 2: count degrees + mark need2 = batch + 1-hop
    k_count_mark<<<(N_EDGES + 255) / 256, 256>>>(edge_row, edge_col);
    // 3-4: scan (block partials, then fused prefix+finalize)
    k_scan1<<<SCAN_NB, SCAN_BLK>>>();
    k_scan3<<<(N_NODES + 255) / 256, 256>>>();
    // 5: fused CSR scatter || p0 = half(dinv * x0)
    k_scatter_init<<<SCATTER_BLOCKS + INIT_BLOCKS, 256>>>(edge_row, edge_col,
                                                          user_emb, item_emb);
    // 6-7: layer 1 full; layer 2 only at marked rows (128-thread blocks, 4 rows each)
    int spmm_blocks = (N_NODES + 3) / 4;
    k_spmm_full<<<spmm_blocks, 128>>>(0, 0);   // p0 -> p1 (all rows)
    k_spmm_full<<<spmm_blocks, 128>>>(1, 1);   // p1 -> p2 (marked rows only)
    // 8: fused sparse layer 3 + outputs (4 batch elems per 128-thread block)
    k_finalize<<<BATCH / 4, 128>>>(users_idx, pos_idx, neg_idx, user_emb, item_emb, out);
}

// round 17
// speedup vs baseline: 1.0926x; 1.0340x over previous
#include <cuda_runtime.h>
#include <cuda_fp16.h>

#define N_USERS 100000
#define N_ITEMS 200000
#define N_NODES (N_USERS + N_ITEMS)
#define DIM 256
#define DIM4 (DIM / 4)
#define DIMH4 (DIM / 8)     // int4 (8 halves) per row = 32
#define N_EDGES 1000000
#define NDIR (2 * N_EDGES)
#define BATCH 8192
#define SCAN_BLK 1024
#define SCAN_NB ((N_NODES + SCAN_BLK - 1) / SCAN_BLK)   // 293
#define SCATTER_BLOCKS ((N_EDGES + 255) / 256)          // 3907
#define INIT_H2 ((size_t)N_NODES * DIM / 2)             // 38.4M half2
#define INIT_BLOCKS ((int)((INIT_H2 + 255) / 256))
#define ZERO_BLOCKS ((N_NODES + 255) / 256)             // 1172
#define MARKB_BLOCKS ((3 * BATCH + 255) / 256)          // 96

// ---------------- device scratch (static: allowed) ----------------
// propagating buffers store p_l = dinv * x_l  (pre-scaled), fp16
__device__ __half g_p0[(size_t)N_NODES * DIM];   // 154 MB
__device__ __half g_p1[(size_t)N_NODES * DIM];   // 154 MB
__device__ __half g_p2[(size_t)N_NODES * DIM];   // 154 MB
__device__ int   g_deg[N_NODES];
__device__ int   g_rowptr[N_NODES + 1];
__device__ int   g_cursor[N_NODES];
__device__ float g_dinv[N_NODES];                // deg^-1/2
__device__ float g_rdeg[N_NODES];                // deg^+1/2 (un-scale factor)
__device__ int   g_csrsrc[NDIR];                 // 8 MB
__device__ int   g_part[SCAN_NB];
// write-once idempotent flags (same batch every call -> identical fixed point)
__device__ unsigned char g_need_b[N_NODES];      // node is a batch node
__device__ unsigned char g_need2[N_NODES];       // p2 needed: batch + 1-hop

// ---------------- accumulator helpers ----------------
struct Acc8 {
    float a0, a1, a2, a3, a4, a5, a6, a7;
    __device__ __forceinline__ void init() {
        a0 = a1 = a2 = a3 = a4 = a5 = a6 = a7 = 0.f;
    }
    __device__ __forceinline__ void add(const int4& raw) {
        float2 f0 = __half22float2(*(__half2*)&raw.x);
        float2 f1 = __half22float2(*(__half2*)&raw.y);
        float2 f2 = __half22float2(*(__half2*)&raw.z);
        float2 f3 = __half22float2(*(__half2*)&raw.w);
        a0 += f0.x; a1 += f0.y; a2 += f1.x; a3 += f1.y;
        a4 += f2.x; a5 += f2.y; a6 += f3.x; a7 += f3.y;
    }
};

// gather-sum over adjacency [beg,end) from fp16 buffer, 4x unrolled for MLP.
// csrsrc uses normal cached loads: all lanes broadcast-read the same element and
// consecutive iterations walk the same 128B line (~32 edges/line) -> real L1 reuse.
__device__ __forceinline__ void gather_sum(const int4* __restrict__ xin, int beg, int end,
                                           int lane, Acc8& acc) {
    int e = beg;
    for (; e + 4 <= end; e += 4) {
        int s0 = g_csrsrc[e];
        int s1 = g_csrsrc[e + 1];
        int s2 = g_csrsrc[e + 2];
        int s3 = g_csrsrc[e + 3];
        int4 r0 = xin[(size_t)s0 * DIMH4 + lane];
        int4 r1 = xin[(size_t)s1 * DIMH4 + lane];
        int4 r2 = xin[(size_t)s2 * DIMH4 + lane];
        int4 r3 = xin[(size_t)s3 * DIMH4 + lane];
        acc.add(r0);
        acc.add(r1);
        acc.add(r2);
        acc.add(r3);
    }
    for (; e < end; e++) {
        int s = g_csrsrc[e];
        int4 r = xin[(size_t)s * DIMH4 + lane];
        acc.add(r);
    }
}

// ---------------- 1: zero degrees + mark batch nodes (disjoint block ranges) ----------
__global__ void k_zero_mark(const int* __restrict__ uidx, const int* __restrict__ pidx,
                            const int* __restrict__ nidx) {
    if (blockIdx.x < ZERO_BLOCKS) {
        int i = blockIdx.x * 256 + threadIdx.x;
        if (i < N_NODES) g_deg[i] = 0;
    } else {
        int j = (blockIdx.x - ZERO_BLOCKS) * 256 + threadIdx.x;
        if (j < 3 * BATCH) {
            int node;
            if (j < BATCH) node = uidx[j];
            else if (j < 2 * BATCH) node = N_USERS + pidx[j - BATCH];
            else node = N_USERS + nidx[j - 2 * BATCH];
            g_need_b[node] = 1;   // idempotent
            g_need2[node] = 1;    // batch nodes need p2 themselves
        }
    }
}

// ---------------- 2: count degrees + mark 1-hop neighbors of batch nodes --------------
__global__ void k_count_mark(const int* __restrict__ erow, const int* __restrict__ ecol) {
    int e = blockIdx.x * blockDim.x + threadIdx.x;
    if (e < N_EDGES) {
        int u = erow[e];
        int it = N_USERS + ecol[e];
        atomicAdd(&g_deg[u], 1);
        atomicAdd(&g_deg[it], 1);
        if (g_need_b[u]) g_need2[it] = 1;   // idempotent byte stores
        if (g_need_b[it]) g_need2[u] = 1;
    }
}

// ---------------- 3: per-block scan (within-block exclusive + block totals) -----------
__global__ void k_scan1() {
    __shared__ int s[SCAN_BLK];
    int tid = threadIdx.x;
    int i = blockIdx.x * SCAN_BLK + tid;
    int v = (i < N_NODES) ? g_deg[i] : 0;
    s[tid] = v;
    __syncthreads();
    for (int off = 1; off < SCAN_BLK; off <<= 1) {
        int t = (tid >= off) ? s[tid - off] : 0;
        __syncthreads();
        s[tid] += t;
        __syncthreads();
    }
    if (i < N_NODES) g_rowptr[i] = s[tid] - v;
    if (tid == SCAN_BLK - 1) g_part[blockIdx.x] = s[tid];
}

// ---------------- 4: finalize scan: inline partial-prefix reduce + dinv/rdeg ----------
// 256-thread blocks; all nodes of a block share one part-prefix (k = blockIdx>>2).
__global__ void __launch_bounds__(256) k_scan3() {
    __shared__ int s[256];
    int tid = threadIdx.x;
    int k = blockIdx.x >> 2;              // number of preceding SCAN_BLK partitions
    int v = 0;
    if (tid < k) v = g_part[tid];
    if (tid + 256 < k) v += g_part[tid + 256];   // k <= 293 < 512
    s[tid] = v;
    __syncthreads();
    for (int off = 128; off > 0; off >>= 1) {
        if (tid < off) s[tid] += s[tid + off];
        __syncthreads();
    }
    int prefix = s[0];

    int i = blockIdx.x * 256 + tid;
    if (i < N_NODES) {
        int rp = g_rowptr[i] + prefix;
        g_rowptr[i] = rp;
        g_cursor[i] = rp;
        int d = g_deg[i];
        float df = (float)(d < 1 ? 1 : d);
        g_dinv[i] = rsqrtf(df);
        g_rdeg[i] = sqrtf(df);
    }
    if (i == 0) g_rowptr[N_NODES] = NDIR;
}

// ---------------- 5: fused CSR scatter (latency-bound) || p0 init (BW-bound) ----------
__global__ void __launch_bounds__(256) k_scatter_init(
        const int* __restrict__ erow, const int* __restrict__ ecol,
        const float* __restrict__ uemb, const float* __restrict__ iemb) {
    if (blockIdx.x < SCATTER_BLOCKS) {
        int e = blockIdx.x * 256 + threadIdx.x;
        if (e < N_EDGES) {
            int u = erow[e];
            int it = N_USERS + ecol[e];
            int p = atomicAdd(&g_cursor[u], 1);
            g_csrsrc[p] = it;
            int q = atomicAdd(&g_cursor[it], 1);
            g_csrsrc[q] = u;
        }
    } else {
        size_t i = (size_t)(blockIdx.x - SCATTER_BLOCKS) * 256 + threadIdx.x;  // half2 idx
        if (i >= INIT_H2) return;
        size_t ei = i * 2;
        size_t row = ei >> 8;
        float d = g_dinv[row];
        float2 v;
        if (ei < (size_t)N_USERS * DIM) v = ((const float2*)uemb)[i];
        else v = ((const float2*)iemb)[i - (size_t)N_USERS * DIM / 2];
        ((__half2*)g_p0)[i] = __floats2half2_rn(v.x * d, v.y * d);
    }
}

// ---------------- 6/7: full propagation, p_out[dst] = half(dinv^2 * sum_src p_in[src]) -
// 128-thread blocks (4 warps), each warp processes 2 CONSECUTIVE rows sequentially:
// sum-of-2-degrees per warp has ~sqrt(2) lower relative spread than a single degree,
// shrinking the CTA max-retire tail; consecutive rows share rowptr/csrsrc lines.
__global__ void __launch_bounds__(128) k_spmm_full(int which, int use_flag) {
    const int4* __restrict__ xin = (const int4*)(which == 0 ? g_p0 : g_p1);
    int4* __restrict__ xout = (int4*)(which == 0 ? g_p1 : g_p2);

    int base = blockIdx.x * 8 + (threadIdx.x >> 5) * 2;
    int lane = threadIdx.x & 31;

#pragma unroll
    for (int r = 0; r < 2; r++) {
        int row = base + r;
        if (row >= N_NODES) break;
        if (use_flag && !g_need2[row]) continue;

        int beg = g_rowptr[row];
        int end = g_rowptr[row + 1];
        float di = g_dinv[row];
        float w = di * di;

        Acc8 acc;
        acc.init();
        gather_sum(xin, beg, end, lane, acc);

        int4 out;
        __half2 o0 = __floats2half2_rn(acc.a0 * w, acc.a1 * w);
        __half2 o1 = __floats2half2_rn(acc.a2 * w, acc.a3 * w);
        __half2 o2 = __floats2half2_rn(acc.a4 * w, acc.a5 * w);
        __half2 o3 = __floats2half2_rn(acc.a6 * w, acc.a7 * w);
        out.x = *(int*)&o0; out.y = *(int*)&o1; out.z = *(int*)&o2; out.w = *(int*)&o3;
        xout[(size_t)row * DIMH4 + lane] = out;   // normal store: re-read by next kernel
    }
}

// ---------------- 8: fused finalize ----------------
__device__ __forceinline__ void load8h(const int4* base, size_t row, int lane, float* f) {
    int4 raw = base[row * DIMH4 + lane];
    float2 f0 = __half22float2(*(__half2*)&raw.x);
    float2 f1 = __half22float2(*(__half2*)&raw.y);
    float2 f2 = __half22float2(*(__half2*)&raw.z);
    float2 f3 = __half22float2(*(__half2*)&raw.w);
    f[0] = f0.x; f[1] = f0.y; f[2] = f1.x; f[3] = f1.y;
    f[4] = f2.x; f[5] = f2.y; f[6] = f3.x; f[7] = f3.y;
}

__device__ __forceinline__ void node_acc(int node, const float4* __restrict__ emb4,
                                         size_t embrow, int lane,
                                         float* accv, float4* __restrict__ rawout) {
    const int4* p1h = (const int4*)g_p1;
    const int4* p2h = (const int4*)g_p2;

    int beg = g_rowptr[node];
    int end = g_rowptr[node + 1];
    float di = g_dinv[node];
    float rd = g_rdeg[node];

    Acc8 acc;
    acc.init();
    gather_sum(p2h, beg, end, lane, acc);
    float x3[8] = {acc.a0 * di, acc.a1 * di, acc.a2 * di, acc.a3 * di,
                   acc.a4 * di, acc.a5 * di, acc.a6 * di, acc.a7 * di};

    float4 e0 = emb4[embrow * DIM4 + lane * 2];
    float4 e1 = emb4[embrow * DIM4 + lane * 2 + 1];
    float e[8] = {e0.x, e0.y, e0.z, e0.w, e1.x, e1.y, e1.z, e1.w};

    float t1[8], t2[8];
    load8h(p1h, (size_t)node, lane, t1);
    load8h(p2h, (size_t)node, lane, t2);
#pragma unroll
    for (int k = 0; k < 8; k++) accv[k] = e[k] + (t1[k] + t2[k]) * rd + x3[k];

    __stcs(&rawout[lane * 2], e0);        // out buffer is write-only: stream it
    __stcs(&rawout[lane * 2 + 1], e1);
}

__global__ void __launch_bounds__(128) k_finalize(
        const int* __restrict__ uidx, const int* __restrict__ pidx,
        const int* __restrict__ nidx,
        const float* __restrict__ uemb, const float* __restrict__ iemb,
        float* __restrict__ out) {
    int b = blockIdx.x * 4 + (threadIdx.x >> 5);
    int lane = threadIdx.x & 31;
    if (b >= BATCH) return;

    int u = uidx[b];
    int pi = pidx[b];
    int ni = nidx[b];

    float4* oue = (float4*)(out + 2 * BATCH) + (size_t)b * DIM4;
    float4* ope = (float4*)(out + 2 * BATCH + (size_t)BATCH * DIM) + (size_t)b * DIM4;
    float4* one_ = (float4*)(out + 2 * BATCH + (size_t)2 * BATCH * DIM) + (size_t)b * DIM4;

    float au[8], ap[8], an[8];
    node_acc(u, (const float4*)uemb, (size_t)u, lane, au, oue);
    node_acc(N_USERS + pi, (const float4*)iemb, (size_t)pi, lane, ap, ope);
    node_acc(N_USERS + ni, (const float4*)iemb, (size_t)ni, lane, an, one_);

    float ps = 0.f, ns = 0.f;
#pragma unroll
    for (int k = 0; k < 8; k++) {
        ps += au[k] * ap[k];
        ns += au[k] * an[k];
    }
#pragma unroll
    for (int off = 16; off > 0; off >>= 1) {
        ps += __shfl_down_sync(0xFFFFFFFFu, ps, off);
        ns += __shfl_down_sync(0xFFFFFFFFu, ns, off);
    }
    const float inv16 = 1.0f / 16.0f;   // (1/(N_LAYERS+1))^2
    if (lane == 0) {
        out[b] = ps * inv16;
        out[BATCH + b] = ns * inv16;
    }
}

// ---------------- launch ----------------
extern "C" void kernel_launch(void* const* d_in, const int* in_sizes, int n_in,
                              void* d_out, int out_size) {
    const float* user_emb = (const float*)d_in[0];
    const float* item_emb = (const float*)d_in[1];
    const int* edge_row = (const int*)d_in[2];
    const int* edge_col = (const int*)d_in[3];
    const int* users_idx = (const int*)d_in[4];
    const int* pos_idx = (const int*)d_in[5];
    const int* neg_idx = (const int*)d_in[6];
    float* out = (float*)d_out;

    // 1: zero degrees + mark batch nodes
    k_zero_mark<<<ZERO_BLOCKS + MARKB_BLOCKS, 256>>>(users_idx, pos_idx, neg_idx);
    // 2: count degrees + mark need2 = batch + 1-hop
    k_count_mark<<<(N_EDGES + 255) / 256, 256>>>(edge_row, edge_col);
    // 3-4: scan (block partials, then fused prefix+finalize)
    k_scan1<<<SCAN_NB, SCAN_BLK>>>();
    k_scan3<<<(N_NODES + 255) / 256, 256>>>();
    // 5: fused CSR scatter || p0 = half(dinv * x0)
    k_scatter_init<<<SCATTER_BLOCKS + INIT_BLOCKS, 256>>>(edge_row, edge_col,
                                                          user_emb, item_emb);
    // 6-7: layer 1 full; layer 2 only at marked rows
    //      (128-thread blocks, 4 warps x 2 consecutive rows = 8 rows per CTA)
    int spmm_blocks = (N_NODES + 7) / 8;
    k_spmm_full<<<spmm_blocks, 128>>>(0, 0);   // p0 -> p1 (all rows)
    k_spmm_full<<<spmm_blocks, 128>>>(1, 1);   // p1 -> p2 (marked rows only)
    // 8: fused sparse layer 3 + outputs (4 batch elems per 128-thread block)
    k_finalize<<<BATCH / 4, 128>>>(users_idx, pos_idx, neg_idx, user_emb, item_emb, out);
}